// round 5
// baseline (speedup 1.0000x reference)
#include <cuda_runtime.h>
#include <math.h>

// ---------------------------------------------------------------------------
// MultiViewSpaTracker forward, fp32, multi-kernel, graph-capturable.
// Key trick: correlation volumes are never materialized; only the 8x8 integer
// window needed by the 7x7 bilinear taps is computed per (plane, level, s, n).
// ---------------------------------------------------------------------------

// Model constants
// S=8, N=128, LAT=128, HID=384, NH=8, NLAYERS=6, DIN=1169, DOUT=387

// ---------------- scratch layout (single __device__ array) -----------------
static constexpr size_t PYR_PLANE   = 5505024;          // L1 4194304 + L2 1048576 + L3 262144
static constexpr size_t OFF_PYR     = 0;
static constexpr size_t OFF_FFEATS  = OFF_PYR + 3*PYR_PLANE;   // [3][8][128][128]
static constexpr size_t OFF_COORDS  = OFF_FFEATS + 393216;     // [8][128][3]
static constexpr size_t OFF_SUPPORT = OFF_COORDS + 3072;       // [100][384]
static constexpr size_t OFF_SPROJ   = OFF_SUPPORT + 38400;     // [100][384]
static constexpr size_t OFF_BIASIN  = OFF_SPROJ + 38400;       // [384]
static constexpr size_t OFF_POS     = OFF_BIASIN + 384;        // [128][1169]
static constexpr size_t OFF_TIMES   = OFF_POS + 149632;        // [8][1169]
static constexpr size_t OFF_TIN     = OFF_TIMES + 9352;        // [1024][1169]
static constexpr size_t OFF_H       = OFF_TIN + 1197056;       // [1024][384]
static constexpr size_t OFF_YLN     = OFF_H + 393216;          // [1024][384]
static constexpr size_t OFF_QKV     = OFF_YLN + 393216;        // [1024][1152]
static constexpr size_t OFF_ATTNO   = OFF_QKV + 1179648;       // [1024][384]
static constexpr size_t OFF_MLP     = OFF_ATTNO + 393216;      // [1024][1536]
static constexpr size_t OFF_DELTA   = OFF_MLP + 1572864;       // [1024][387]
static constexpr size_t OFF_GN      = OFF_DELTA + 396288;      // [3][1024][128]
static constexpr size_t OFF_UPD     = OFF_GN + 3*131072;       // [3][1024][128]
static constexpr size_t SCRATCH_TOT = OFF_UPD + 3*131072;

__device__ float g_scratch[SCRATCH_TOT];

// ---------------------------- small kernels --------------------------------

// 2x2 average pool: src is (1024 maps, 2Ho, 2Wo) -> dst (1024, Ho, Wo)
__global__ void k_down(const float* __restrict__ src, float* __restrict__ dst,
                       int Ho, int Wo) {
    int idx = blockIdx.x * blockDim.x + threadIdx.x;
    int total = 1024 * Ho * Wo;
    if (idx >= total) return;
    int x = idx % Wo;
    int y = (idx / Wo) % Ho;
    int m = idx / (Wo * Ho);
    int Wsrc = Wo * 2;
    const float* p = src + ((size_t)m * (Ho * 2) + y * 2) * Wsrc + x * 2;
    dst[idx] = 0.25f * (p[0] + p[1] + p[Wsrc] + p[Wsrc + 1]);
}

// positional embedding from coords_init[:,0] (s=0 slice): per point n, 1169 cols
__global__ void k_pos(const float* __restrict__ ci, float* __restrict__ pos) {
    int n = blockIdx.x;
    for (int col = threadIdx.x; col < 1169; col += blockDim.x) {
        int i = col / 390, j = col % 390;
        float g = ci[n * 3 + i] * 2.0f - 128.0f;   // (c/128*2-1)*128
        int jj = (j < 195) ? j : j - 195;
        float om = expf(-9.210340371976184f * (float)jj / 195.0f); // 10000^{-jj/195}
        float ang = g * om;
        pos[(size_t)n * 1169 + col] = (j < 195) ? sinf(ang) : cosf(ang);
    }
}

// time embedding: sincos1d(1170, s)[:1169]
__global__ void k_times(float* __restrict__ tim) {
    int s = blockIdx.x;
    float p = (float)s;
    for (int col = threadIdx.x; col < 1169; col += blockDim.x) {
        int jj = (col < 585) ? col : col - 585;
        float om = expf(-9.210340371976184f * (float)jj / 585.0f);
        float ang = p * om;
        tim[(size_t)s * 1169 + col] = (col < 585) ? sinf(ang) : cosf(ang);
    }
}

// init mutable state each launch (graph replays!)
__global__ void k_init(const float* __restrict__ ci, const float* __restrict__ sf,
                       const float* __restrict__ fi,
                       float* __restrict__ coords, float* __restrict__ support,
                       float* __restrict__ ffeats) {
    for (int idx = blockIdx.x * blockDim.x + threadIdx.x; idx < 393216;
         idx += gridDim.x * blockDim.x) {
        // ffeats flat = ((k*8+s)*128+n)*128+c = k*131072 + s*16384 + n*128 + c
        int k = idx / 131072;
        int r = idx % 131072;
        int s = r / 16384;
        int r2 = r % 16384;
        int n = r2 >> 7;
        int c = r2 & 127;
        ffeats[idx] = fi[(((size_t)(s * 128 + n)) * 128 + c) * 3 + k];
        if (idx < 3072) coords[idx] = ci[idx];
        if (idx < 38400) support[idx] = sf[idx];
    }
}

// Correlation sampling: one block per (plane, level, s, n); computes the 8x8
// integer window of dot products then 49 bilinear taps directly into tin.
__global__ void k_corr(const float* __restrict__ fmXY, const float* __restrict__ fmYZ,
                       const float* __restrict__ fmXZ, const float* __restrict__ pyr,
                       const float* __restrict__ ffeats, const float* __restrict__ coords,
                       float* __restrict__ tin) {
    int b = blockIdx.x;
    int sn = b & 1023;
    int lvl = (b >> 10) & 3;
    int pl = b >> 12;
    int s = sn >> 7, n = sn & 127;
    int size = 128 >> lvl;
    const float* fm;
    if (lvl == 0) {
        const float* base = (pl == 0) ? fmXY : ((pl == 1) ? fmYZ : fmXZ);
        fm = base;
    } else {
        size_t off = (lvl == 1) ? 0 : ((lvl == 2) ? 4194304 : 5242880);
        fm = pyr + (size_t)pl * PYR_PLANE + off;
    }
    float c0 = coords[(s * 128 + n) * 3 + 0];
    float c1 = coords[(s * 128 + n) * 3 + 1];
    float c2 = coords[(s * 128 + n) * 3 + 2];
    float cx, cy;
    if (pl == 0)      { cx = c0; cy = c1; }
    else if (pl == 1) { cx = c1; cy = c2; }
    else              { cx = c0; cy = c2; }
    float scl = exp2f(-(float)lvl);
    cx *= scl; cy *= scl;
    float fx0 = floorf(cx), fy0 = floorf(cy);
    float wx = cx - fx0, wy = cy - fy0;
    int x0 = (int)fx0, y0 = (int)fy0;

    __shared__ float tgt[128];
    __shared__ float G[64];
    int tid = threadIdx.x;                 // 64 threads
    tgt[tid]      = ffeats[(((size_t)(pl * 8 + s)) * 128 + n) * 128 + tid];
    tgt[tid + 64] = ffeats[(((size_t)(pl * 8 + s)) * 128 + n) * 128 + tid + 64];
    __syncthreads();

    int ix = tid & 7, iy = tid >> 3;
    int px = x0 - 3 + ix, py = y0 - 3 + iy;
    float dot = 0.0f;
    if (px >= 0 && px < size && py >= 0 && py < size) {
        size_t cs = (size_t)size * size;
        const float* fp = fm + ((size_t)s * 128) * cs + (size_t)py * size + px;
        #pragma unroll 8
        for (int c = 0; c < 128; c++) dot += tgt[c] * fp[(size_t)c * cs];
    }
    G[iy * 8 + ix] = dot * 0.08838834764831845f;   // 1/sqrt(128)
    __syncthreads();

    if (tid < 49) {
        int kx = tid / 7, ky = tid % 7;    // x offset idx, y offset idx
        float g00 = G[ky * 8 + kx];
        float g10 = G[ky * 8 + kx + 1];
        float g01 = G[(ky + 1) * 8 + kx];
        float g11 = G[(ky + 1) * 8 + kx + 1];
        float v = g00 * (1 - wx) * (1 - wy) + g10 * wx * (1 - wy) +
                  g01 * (1 - wx) * wy + g11 * wx * wy;
        tin[(size_t)(n * 8 + s) * 1169 + 195 + pl * 196 + lvl * 49 + tid] = v;
    }
}

// Assemble tin: flow embed, ffeats, tmv columns; add pos + time embeddings to all
__global__ void k_assemble(float* __restrict__ tin, const float* __restrict__ coords,
                           const float* __restrict__ ffeats, const float* __restrict__ pos,
                           const float* __restrict__ tim, const float* __restrict__ track_mask,
                           const float* __restrict__ vis_init) {
    int ns = blockIdx.x;
    int n = ns >> 3, s = ns & 7;
    __shared__ float f[3];
    if (threadIdx.x < 3)
        f[threadIdx.x] = coords[(s * 128 + n) * 3 + threadIdx.x] - coords[n * 3 + threadIdx.x];
    __syncthreads();
    size_t row = (size_t)(n * 8 + s) * 1169;
    for (int col = threadIdx.x; col < 1169; col += blockDim.x) {
        float v;
        if (col < 192) {
            int a = col / 64, r = col % 64, q = r >> 1;
            float ang = f[a] * (31.25f * (float)q);
            v = (r & 1) ? cosf(ang) : sinf(ang);
        } else if (col < 195) {
            v = f[col - 192];
        } else if (col < 783) {
            v = tin[row + col];                 // fcorr written by k_corr
        } else if (col < 1167) {
            int c = col - 783;
            int k = c >> 7, cc = c & 127;
            v = ffeats[(((size_t)(k * 8 + s)) * 128 + n) * 128 + cc];
        } else {
            int c2 = col - 1167;
            int fidx = n * 16 + s * 2 + c2;     // reshape scramble of concat(mask,vis)
            int p = fidx >> 3, sp = fidx & 7;
            v = (p < 128) ? track_mask[sp * 128 + p] : vis_init[sp * 128 + (p - 128)];
        }
        tin[row + col] = v + pos[(size_t)n * 1169 + col] + tim[(size_t)s * 1169 + col];
    }
}

// ------------------------------ GEMM ---------------------------------------
// C[M,N] = act(A[M,K] @ B[K,N] + bias) + resid     (any ptr may be null)
// Batched via blockIdx.z with per-batch element strides (0/1-batch = plain).
// Software-pipelined: next k-tile's LDGs are issued before the FFMA block so
// L2/DRAM latency overlaps compute. A-tile row padded to 68 floats (272B,
// 16B-multiple) so operand fetches are LDS.128.
__global__ __launch_bounds__(256) void gemm_k(
    const float* __restrict__ A, const float* __restrict__ B,
    const float* __restrict__ bias,
    const float* __restrict__ resid, float* __restrict__ C,
    int M, int N, int K, int act,
    size_t As_, size_t Bs_, size_t bs_, size_t Cs_) {
    __shared__ float As[16][68];
    __shared__ float Bs[16][64];
    int z = blockIdx.z;
    A += (size_t)z * As_;
    B += (size_t)z * Bs_;
    if (bias) bias += (size_t)z * bs_;
    C += (size_t)z * Cs_;
    int tid = threadIdx.x;
    int tx = tid & 15, ty = tid >> 4;
    int m0 = blockIdx.y * 64, n0 = blockIdx.x * 64;
    float acc[4][4] = {};
    float ra[4], rb[4];

    // prologue: load k-tile 0 into registers
    #pragma unroll
    for (int r = 0; r < 4; r++) {
        int li = tid + r * 256;
        int i = li >> 4, j = li & 15;
        int mm = m0 + i;
        ra[r] = (mm < M && j < K) ? A[(size_t)mm * K + j] : 0.0f;
        int bi = li >> 6, bj = li & 63;
        int nn = n0 + bj;
        rb[r] = (bi < K && nn < N) ? B[(size_t)bi * N + nn] : 0.0f;
    }

    for (int k0 = 0; k0 < K; k0 += 16) {
        // commit prefetched tile to smem
        #pragma unroll
        for (int r = 0; r < 4; r++) {
            int li = tid + r * 256;
            As[li & 15][li >> 4] = ra[r];
            Bs[li >> 6][li & 63] = rb[r];
        }
        __syncthreads();
        // prefetch next k-tile (issued before compute; latency overlapped)
        int kn = k0 + 16;
        if (kn < K) {
            #pragma unroll
            for (int r = 0; r < 4; r++) {
                int li = tid + r * 256;
                int i = li >> 4, j = li & 15;
                int mm = m0 + i, kk = kn + j;
                ra[r] = (mm < M && kk < K) ? A[(size_t)mm * K + kk] : 0.0f;
                int bi = li >> 6, bj = li & 63;
                int kb = kn + bi, nn = n0 + bj;
                rb[r] = (kb < K && nn < N) ? B[(size_t)kb * N + nn] : 0.0f;
            }
        }
        #pragma unroll
        for (int kk = 0; kk < 16; kk++) {
            float4 av = *reinterpret_cast<const float4*>(&As[kk][ty * 4]);
            float4 bv = *reinterpret_cast<const float4*>(&Bs[kk][tx * 4]);
            acc[0][0] += av.x * bv.x; acc[0][1] += av.x * bv.y; acc[0][2] += av.x * bv.z; acc[0][3] += av.x * bv.w;
            acc[1][0] += av.y * bv.x; acc[1][1] += av.y * bv.y; acc[1][2] += av.y * bv.z; acc[1][3] += av.y * bv.w;
            acc[2][0] += av.z * bv.x; acc[2][1] += av.z * bv.y; acc[2][2] += av.z * bv.z; acc[2][3] += av.z * bv.w;
            acc[3][0] += av.w * bv.x; acc[3][1] += av.w * bv.y; acc[3][2] += av.w * bv.z; acc[3][3] += av.w * bv.w;
        }
        __syncthreads();
    }
    #pragma unroll
    for (int r = 0; r < 4; r++) {
        int row = m0 + ty * 4 + r;
        if (row >= M) continue;
        #pragma unroll
        for (int c = 0; c < 4; c++) {
            int col = n0 + tx * 4 + c;
            if (col >= N) continue;
            float v = acc[r][c];
            if (bias)  v += bias[col];
            if (act == 1) v = 0.5f * v * (1.0f + erff(v * 0.70710678118654752f));
            if (resid) v += resid[(size_t)row * N + col];
            C[(size_t)row * N + col] = v;
        }
    }
}

static inline void gemm(const float* A, const float* B, const float* bias,
                        const float* resid, float* C,
                        int M, int N, int K, int act) {
    dim3 grid((N + 63) / 64, (M + 63) / 64, 1);
    gemm_k<<<grid, 256>>>(A, B, bias, resid, C, M, N, K, act, 0, 0, 0, 0);
}

static inline void gemm_batched3(const float* A, const float* B, const float* bias,
                                 float* C, int M, int N, int K, int act,
                                 size_t As_, size_t Bs_, size_t bs_, size_t Cs_) {
    dim3 grid((N + 63) / 64, (M + 63) / 64, 3);
    gemm_k<<<grid, 256>>>(A, B, bias, nullptr, C, M, N, K, act, As_, Bs_, bs_, Cs_);
}

// support-proj mean + combined W_in bias
__global__ void k_spmean(const float* __restrict__ sproj, const float* __restrict__ b_in,
                         float* __restrict__ biasin) {
    int c = threadIdx.x;
    if (c >= 384) return;
    float s = 0.0f;
    for (int r = 0; r < 100; r++) s += sproj[r * 384 + c];
    biasin[c] = b_in[c] + s * 0.01f;
}

__global__ void k_supp(float* __restrict__ support, const float* __restrict__ sproj) {
    int idx = blockIdx.x * blockDim.x + threadIdx.x;
    if (idx < 38400) support[idx] += sproj[idx] * 0.01f;
}

// LayerNorm / GroupNorm over last dim C; input row stride xs, column offset xo
__global__ void k_norm(const float* __restrict__ x, float* __restrict__ y,
                       const float* __restrict__ gw, const float* __restrict__ bw,
                       int C, int xs, int xo) {
    int r = blockIdx.x;
    const float* xp = x + (size_t)r * xs + xo;
    float s = 0.0f, ss = 0.0f;
    for (int c = threadIdx.x; c < C; c += blockDim.x) {
        float v = xp[c];
        s += v; ss += v * v;
    }
    __shared__ float sh1[32], sh2[32];
    int lane = threadIdx.x & 31, w = threadIdx.x >> 5;
    #pragma unroll
    for (int o = 16; o; o >>= 1) {
        s += __shfl_down_sync(0xffffffffu, s, o);
        ss += __shfl_down_sync(0xffffffffu, ss, o);
    }
    if (lane == 0) { sh1[w] = s; sh2[w] = ss; }
    __syncthreads();
    int nw = blockDim.x >> 5;
    if (w == 0) {
        s = (lane < nw) ? sh1[lane] : 0.0f;
        ss = (lane < nw) ? sh2[lane] : 0.0f;
        #pragma unroll
        for (int o = 16; o; o >>= 1) {
            s += __shfl_down_sync(0xffffffffu, s, o);
            ss += __shfl_down_sync(0xffffffffu, ss, o);
        }
        if (lane == 0) { sh1[0] = s; sh2[0] = ss; }
    }
    __syncthreads();
    float m = sh1[0] / (float)C;
    float var = sh2[0] / (float)C - m * m;
    float inv = rsqrtf(var + 1e-5f);
    for (int c = threadIdx.x; c < C; c += blockDim.x)
        y[(size_t)r * C + c] = (xp[c] - m) * inv * gw[c] + bw[c];
}

// Batched GroupNorm for the 3 feature-update chains: one warp per (k, row).
// Block = 4 warps -> 4 rows. Grid = 3*1024/4 = 768 blocks.
__global__ __launch_bounds__(128) void k_norm3(const float* __restrict__ del,
                                               const float* __restrict__ gn_g,
                                               const float* __restrict__ gn_b,
                                               float* __restrict__ gn) {
    int row4 = blockIdx.x * 4 + (threadIdx.x >> 5);   // 0..3071
    int k = row4 / 1024, r = row4 % 1024;
    int lane = threadIdx.x & 31;
    const float* xp = del + (size_t)r * 387 + 3 + k * 128;
    float v0 = xp[lane], v1 = xp[lane + 32], v2 = xp[lane + 64], v3 = xp[lane + 96];
    float s = v0 + v1 + v2 + v3;
    float ss = v0 * v0 + v1 * v1 + v2 * v2 + v3 * v3;
    #pragma unroll
    for (int o = 16; o; o >>= 1) {
        s += __shfl_xor_sync(0xffffffffu, s, o);
        ss += __shfl_xor_sync(0xffffffffu, ss, o);
    }
    float m = s / 128.0f;
    float var = ss / 128.0f - m * m;
    float inv = rsqrtf(var + 1e-5f);
    const float* g = gn_g + k * 128;
    const float* b = gn_b + k * 128;
    float* yp = gn + (size_t)k * 131072 + (size_t)r * 128;
    yp[lane]      = (v0 - m) * inv * g[lane]      + b[lane];
    yp[lane + 32] = (v1 - m) * inv * g[lane + 32] + b[lane + 32];
    yp[lane + 64] = (v2 - m) * inv * g[lane + 64] + b[lane + 64];
    yp[lane + 96] = (v3 - m) * inv * g[lane + 96] + b[lane + 96];
}

// Attention, even layers: groups = points (m=n, 128 blocks), T=8, NH=8, dh=48.
// Thread = (head, t). Full qkv tile for the group in smem (8*1152 floats).
__global__ __launch_bounds__(64) void k_attn8(const float* __restrict__ qkv,
                                              float* __restrict__ o) {
    int m = blockIdx.x;
    __shared__ float sm[8 * 1152];
    int tid = threadIdx.x;
    for (int i = tid; i < 8 * 1152; i += 64)
        sm[i] = qkv[(size_t)(m * 8 + i / 1152) * 1152 + (i % 1152)];
    __syncthreads();
    int h = tid >> 3, t = tid & 7;
    const float* q = sm + t * 1152 + h * 48;
    float sc[8];
    float mx = -1e30f;
    #pragma unroll
    for (int u = 0; u < 8; u++) {
        const float* kk = sm + u * 1152 + 384 + h * 48;
        float d = 0.0f;
        #pragma unroll
        for (int j = 0; j < 48; j++) d += q[j] * kk[j];
        d *= 0.14433756729740643f;    // 1/sqrt(48)
        sc[u] = d;
        mx = fmaxf(mx, d);
    }
    float sum = 0.0f;
    #pragma unroll
    for (int u = 0; u < 8; u++) { sc[u] = expf(sc[u] - mx); sum += sc[u]; }
    float inv = 1.0f / sum;
    for (int j = 0; j < 48; j++) {
        float a = 0.0f;
        #pragma unroll
        for (int u = 0; u < 8; u++) a += sc[u] * sm[u * 1152 + 768 + h * 48 + j];
        o[(size_t)(m * 8 + t) * 384 + h * 48 + j] = a * inv;
    }
}

// Attention, odd layers: groups = time (s), tokens = points (128). Block per (s,h).
// Rows in the n-major buffer: token u -> row u*8+s.
// K resident in smem (24KB); V streamed in 2 chunks of 64 tokens (12KB).
// Scores recomputed per chunk from smem-resident K (cheap, FFMA-bound).
__global__ __launch_bounds__(128) void k_attn128(const float* __restrict__ qkv,
                                                 float* __restrict__ o) {
    int s = blockIdx.x >> 3, h = blockIdx.x & 7;
    __shared__ float ks[128 * 48];     // 24 KB
    __shared__ float vs[64 * 48];      // 12 KB
    int t = threadIdx.x;
    for (int i = t; i < 128 * 48; i += 128) {
        int u = i / 48, j = i % 48;
        ks[i] = qkv[(size_t)(u * 8 + s) * 1152 + 384 + h * 48 + j];
    }
    __syncthreads();
    float q[48];
    size_t qrow = (size_t)(t * 8 + s) * 1152 + h * 48;
    #pragma unroll
    for (int j = 0; j < 48; j++) q[j] = qkv[qrow + j];
    const float scale = 0.14433756729740643f;
    float mx = -1e30f;
    for (int u = 0; u < 128; u++) {
        float d = 0.0f;
        #pragma unroll
        for (int j = 0; j < 48; j++) d += q[j] * ks[u * 48 + j];
        mx = fmaxf(mx, d * scale);
    }
    float sum = 0.0f;
    float out[48];
    #pragma unroll
    for (int j = 0; j < 48; j++) out[j] = 0.0f;
    for (int ch = 0; ch < 2; ch++) {
        __syncthreads();
        for (int i = t; i < 64 * 48; i += 128) {
            int u = i / 48, j = i % 48;
            vs[i] = qkv[(size_t)((ch * 64 + u) * 8 + s) * 1152 + 768 + h * 48 + j];
        }
        __syncthreads();
        for (int u = 0; u < 64; u++) {
            float d = 0.0f;
            const float* kp = ks + (ch * 64 + u) * 48;
            #pragma unroll
            for (int j = 0; j < 48; j++) d += q[j] * kp[j];
            float p = expf(d * scale - mx);
            sum += p;
            #pragma unroll
            for (int j = 0; j < 48; j++) out[j] += p * vs[u * 48 + j];
        }
    }
    float inv = 1.0f / sum;
    size_t orow = (size_t)(t * 8 + s) * 384 + h * 48;
    #pragma unroll
    for (int j = 0; j < 48; j++) o[orow + j] = out[j] * inv;
}

__global__ void k_coords(float* __restrict__ coords, const float* __restrict__ delta) {
    int idx = blockIdx.x * blockDim.x + threadIdx.x;
    if (idx >= 3072) return;
    int sn = idx / 3, a = idx % 3;
    int s = sn >> 7, n = sn & 127;
    coords[idx] += delta[(size_t)(n * 8 + s) * 387 + a];
}

// Batched ffeats += gelu'd update, all 3 planes in one launch.
__global__ void k_ffadd3(float* __restrict__ ffeats, const float* __restrict__ upd) {
    int idx = blockIdx.x * blockDim.x + threadIdx.x;
    if (idx >= 393216) return;
    int k = idx / 131072;
    int r = idx % 131072;
    int n = r >> 10;
    int s = (r >> 7) & 7;
    int c = r & 127;
    ffeats[(((size_t)(k * 8 + s)) * 128 + n) * 128 + c] += upd[idx];
}

__global__ void k_vis(const float* __restrict__ ffeats, const float* __restrict__ coords,
                      const float* __restrict__ Wvis, const float* __restrict__ bvis,
                      float* __restrict__ out) {
    int sn = blockIdx.x;
    int s = sn >> 7, n = sn & 127;
    float acc = 0.0f;
    for (int c = threadIdx.x; c < 384; c += blockDim.x) {
        int k = c >> 7, cc = c & 127;
        acc += ffeats[(((size_t)(k * 8 + s)) * 128 + n) * 128 + cc] * Wvis[c];
    }
    __shared__ float sh[32];
    int lane = threadIdx.x & 31, w = threadIdx.x >> 5;
    #pragma unroll
    for (int o = 16; o; o >>= 1) acc += __shfl_down_sync(0xffffffffu, acc, o);
    if (lane == 0) sh[w] = acc;
    __syncthreads();
    if (threadIdx.x == 0) {
        float t = 0.0f;
        int nw = blockDim.x >> 5;
        for (int i = 0; i < nw; i++) t += sh[i];
        out[sn * 4 + 3] = t + bvis[0];
    }
    if (threadIdx.x < 3) out[sn * 4 + threadIdx.x] = coords[sn * 3 + threadIdx.x];
}

// ------------------------------- host --------------------------------------

extern "C" void kernel_launch(void* const* d_in, const int* in_sizes, int n_in,
                              void* d_out, int out_size) {
    const float* fmXY        = (const float*)d_in[0];
    const float* fmYZ        = (const float*)d_in[1];
    const float* fmXZ        = (const float*)d_in[2];
    const float* coords_init = (const float*)d_in[3];
    const float* vis_init    = (const float*)d_in[4];
    const float* track_mask  = (const float*)d_in[5];
    const float* feat_init   = (const float*)d_in[6];
    const float* support_in  = (const float*)d_in[7];
    int i8 = (in_sizes[8] == 1) ? 9 : 8;    // skip `iters` scalar if present
    const float* W_in  = (const float*)d_in[i8 + 0];
    const float* b_in  = (const float*)d_in[i8 + 1];
    const float* lnp   = (const float*)d_in[i8 + 2];
    const float* Wqkv  = (const float*)d_in[i8 + 3];
    const float* bqkv  = (const float*)d_in[i8 + 4];
    const float* Wo    = (const float*)d_in[i8 + 5];
    const float* bo    = (const float*)d_in[i8 + 6];
    const float* W1    = (const float*)d_in[i8 + 7];
    const float* b1    = (const float*)d_in[i8 + 8];
    const float* W2    = (const float*)d_in[i8 + 9];
    const float* b2    = (const float*)d_in[i8 + 10];
    const float* W_out = (const float*)d_in[i8 + 11];
    const float* b_out = (const float*)d_in[i8 + 12];
    const float* Ws    = (const float*)d_in[i8 + 13];
    const float* bs    = (const float*)d_in[i8 + 14];
    const float* gn_g  = (const float*)d_in[i8 + 15];
    const float* gn_b  = (const float*)d_in[i8 + 16];
    const float* Wu    = (const float*)d_in[i8 + 17];
    const float* bu    = (const float*)d_in[i8 + 18];
    const float* Wvis  = (const float*)d_in[i8 + 19];
    const float* bvis  = (const float*)d_in[i8 + 20];
    float* out = (float*)d_out;

    float* sc = nullptr;
    cudaGetSymbolAddress((void**)&sc, g_scratch);
    float* PYR = sc + OFF_PYR;
    float* FF  = sc + OFF_FFEATS;
    float* CR  = sc + OFF_COORDS;
    float* SUP = sc + OFF_SUPPORT;
    float* SPJ = sc + OFF_SPROJ;
    float* BIN = sc + OFF_BIASIN;
    float* POS = sc + OFF_POS;
    float* TIM = sc + OFF_TIMES;
    float* TIN = sc + OFF_TIN;
    float* H   = sc + OFF_H;
    float* YLN = sc + OFF_YLN;
    float* QKV = sc + OFF_QKV;
    float* AO  = sc + OFF_ATTNO;
    float* MLP = sc + OFF_MLP;
    float* DEL = sc + OFF_DELTA;
    float* GN  = sc + OFF_GN;
    float* UPD = sc + OFF_UPD;

    // Pyramids (levels 1..3) for the three planes
    const float* fms[3] = {fmXY, fmYZ, fmXZ};
    for (int pl = 0; pl < 3; pl++) {
        float* p1 = PYR + (size_t)pl * PYR_PLANE;
        float* p2 = p1 + 4194304;
        float* p3 = p2 + 1048576;
        k_down<<<(1024 * 64 * 64 + 255) / 256, 256>>>(fms[pl], p1, 64, 64);
        k_down<<<(1024 * 32 * 32 + 255) / 256, 256>>>(p1, p2, 32, 32);
        k_down<<<(1024 * 16 * 16 + 255) / 256, 256>>>(p2, p3, 16, 16);
    }
    k_pos<<<128, 256>>>(coords_init, POS);
    k_times<<<8, 256>>>(TIM);
    k_init<<<768, 512>>>(coords_init, support_in, feat_init, CR, SUP, FF);

    for (int it = 0; it < 2; it++) {
        k_corr<<<12288, 64>>>(fmXY, fmYZ, fmXZ, PYR, FF, CR, TIN);
        k_assemble<<<1024, 128>>>(TIN, CR, FF, POS, TIM, track_mask, vis_init);

        // support projection + mean + support update (sproj uses pre-update support)
        gemm(SUP, Ws, bs, nullptr, SPJ, 100, 384, 384, 0);
        k_spmean<<<1, 384>>>(SPJ, b_in, BIN);
        k_supp<<<150, 256>>>(SUP, SPJ);

        // h = tin @ W_in + (b_in + sproj.mean)
        gemm(TIN, W_in, BIN, nullptr, H, 1024, 384, 1169, 0);

        for (int i = 0; i < 6; i++) {
            const float* Wq  = Wqkv + (size_t)i * 384 * 1152;
            const float* bq  = bqkv + (size_t)i * 1152;
            const float* Woi = Wo   + (size_t)i * 384 * 384;
            const float* boi = bo   + (size_t)i * 384;
            const float* W1i = W1   + (size_t)i * 384 * 1536;
            const float* b1i = b1   + (size_t)i * 1536;
            const float* W2i = W2   + (size_t)i * 1536 * 384;
            const float* b2i = b2   + (size_t)i * 384;
            const float* ln  = lnp  + (size_t)i * 4 * 384;

            k_norm<<<1024, 128>>>(H, YLN, ln, ln + 384, 384, 384, 0);
            gemm(YLN, Wq, bq, nullptr, QKV, 1024, 1152, 384, 0);
            if ((i & 1) == 0) k_attn8<<<128, 64>>>(QKV, AO);
            else              k_attn128<<<64, 128>>>(QKV, AO);
            gemm(AO, Woi, boi, H, H, 1024, 384, 384, 0);

            k_norm<<<1024, 128>>>(H, YLN, ln + 768, ln + 1152, 384, 384, 0);
            gemm(YLN, W1i, b1i, nullptr, MLP, 1024, 1536, 384, 1);
            gemm(MLP, W2i, b2i, H, H, 1024, 384, 1536, 0);
        }

        gemm(H, W_out, b_out, nullptr, DEL, 1024, 387, 384, 0);
        k_coords<<<12, 256>>>(CR, DEL);
        // batched feature update: GN -> GEMM(+gelu) -> add, all 3 planes per launch
        k_norm3<<<768, 128>>>(DEL, gn_g, gn_b, GN);
        gemm_batched3(GN, Wu, bu, UPD, 1024, 128, 128, 1,
                      131072, 16384, 128, 131072);
        k_ffadd3<<<1536, 256>>>(FF, UPD);
    }
    k_vis<<<1024, 128>>>(FF, CR, Wvis, bvis, out);
}

// round 11
// speedup vs baseline: 1.5234x; 1.5234x over previous
#include <cuda_runtime.h>
#include <cuda_bf16.h>
#include <mma.h>
#include <math.h>

using namespace nvcuda;

// ---------------------------------------------------------------------------
// MultiViewSpaTracker forward. GEMMs on tensor cores (wmma bf16 hi/lo split,
// fp32-equivalent accuracy ~1e-4). Correlation volumes never materialized.
// ---------------------------------------------------------------------------

// Model constants: S=8, N=128, LAT=128, HID=384, NH=8, NLAYERS=6, DIN=1169, DOUT=387

// ---------------- scratch layout (single __device__ array) -----------------
static constexpr size_t PYR_PLANE   = 5505024;
static constexpr size_t OFF_PYR     = 0;
static constexpr size_t OFF_FFEATS  = OFF_PYR + 3*PYR_PLANE;
static constexpr size_t OFF_COORDS  = OFF_FFEATS + 393216;
static constexpr size_t OFF_SUPPORT = OFF_COORDS + 3072;
static constexpr size_t OFF_SPROJ   = OFF_SUPPORT + 38400;
static constexpr size_t OFF_BIASIN  = OFF_SPROJ + 38400;
static constexpr size_t OFF_POS     = OFF_BIASIN + 384;
static constexpr size_t OFF_TIMES   = OFF_POS + 149632;
static constexpr size_t OFF_TIN     = OFF_TIMES + 9352;
static constexpr size_t OFF_H       = OFF_TIN + 1197056;
static constexpr size_t OFF_YLN     = OFF_H + 393216;
static constexpr size_t OFF_QKV     = OFF_YLN + 393216;
static constexpr size_t OFF_ATTNO   = OFF_QKV + 1179648;
static constexpr size_t OFF_MLP     = OFF_ATTNO + 393216;
static constexpr size_t OFF_DELTA   = OFF_MLP + 1572864;
static constexpr size_t OFF_GN      = OFF_DELTA + 396288;
static constexpr size_t OFF_UPD     = OFF_GN + 3*131072;
static constexpr size_t SCRATCH_TOT = OFF_UPD + 3*131072;

__device__ float g_scratch[SCRATCH_TOT];

// ---------------------------- small kernels --------------------------------

__global__ void k_down(const float* __restrict__ src, float* __restrict__ dst,
                       int Ho, int Wo) {
    int idx = blockIdx.x * blockDim.x + threadIdx.x;
    int total = 1024 * Ho * Wo;
    if (idx >= total) return;
    int x = idx % Wo;
    int y = (idx / Wo) % Ho;
    int m = idx / (Wo * Ho);
    int Wsrc = Wo * 2;
    const float* p = src + ((size_t)m * (Ho * 2) + y * 2) * Wsrc + x * 2;
    dst[idx] = 0.25f * (p[0] + p[1] + p[Wsrc] + p[Wsrc + 1]);
}

__global__ void k_pos(const float* __restrict__ ci, float* __restrict__ pos) {
    int n = blockIdx.x;
    for (int col = threadIdx.x; col < 1169; col += blockDim.x) {
        int i = col / 390, j = col % 390;
        float g = ci[n * 3 + i] * 2.0f - 128.0f;
        int jj = (j < 195) ? j : j - 195;
        float om = expf(-9.210340371976184f * (float)jj / 195.0f);
        float ang = g * om;
        pos[(size_t)n * 1169 + col] = (j < 195) ? sinf(ang) : cosf(ang);
    }
}

__global__ void k_times(float* __restrict__ tim) {
    int s = blockIdx.x;
    float p = (float)s;
    for (int col = threadIdx.x; col < 1169; col += blockDim.x) {
        int jj = (col < 585) ? col : col - 585;
        float om = expf(-9.210340371976184f * (float)jj / 585.0f);
        float ang = p * om;
        tim[(size_t)s * 1169 + col] = (col < 585) ? sinf(ang) : cosf(ang);
    }
}

__global__ void k_init(const float* __restrict__ ci, const float* __restrict__ sf,
                       const float* __restrict__ fi,
                       float* __restrict__ coords, float* __restrict__ support,
                       float* __restrict__ ffeats) {
    for (int idx = blockIdx.x * blockDim.x + threadIdx.x; idx < 393216;
         idx += gridDim.x * blockDim.x) {
        int k = idx / 131072;
        int r = idx % 131072;
        int s = r / 16384;
        int r2 = r % 16384;
        int n = r2 >> 7;
        int c = r2 & 127;
        ffeats[idx] = fi[(((size_t)(s * 128 + n)) * 128 + c) * 3 + k];
        if (idx < 3072) coords[idx] = ci[idx];
        if (idx < 38400) support[idx] = sf[idx];
    }
}

__global__ void k_corr(const float* __restrict__ fmXY, const float* __restrict__ fmYZ,
                       const float* __restrict__ fmXZ, const float* __restrict__ pyr,
                       const float* __restrict__ ffeats, const float* __restrict__ coords,
                       float* __restrict__ tin) {
    int b = blockIdx.x;
    int sn = b & 1023;
    int lvl = (b >> 10) & 3;
    int pl = b >> 12;
    int s = sn >> 7, n = sn & 127;
    int size = 128 >> lvl;
    const float* fm;
    if (lvl == 0) {
        const float* base = (pl == 0) ? fmXY : ((pl == 1) ? fmYZ : fmXZ);
        fm = base;
    } else {
        size_t off = (lvl == 1) ? 0 : ((lvl == 2) ? 4194304 : 5242880);
        fm = pyr + (size_t)pl * PYR_PLANE + off;
    }
    float c0 = coords[(s * 128 + n) * 3 + 0];
    float c1 = coords[(s * 128 + n) * 3 + 1];
    float c2 = coords[(s * 128 + n) * 3 + 2];
    float cx, cy;
    if (pl == 0)      { cx = c0; cy = c1; }
    else if (pl == 1) { cx = c1; cy = c2; }
    else              { cx = c0; cy = c2; }
    float scl = exp2f(-(float)lvl);
    cx *= scl; cy *= scl;
    float fx0 = floorf(cx), fy0 = floorf(cy);
    float wx = cx - fx0, wy = cy - fy0;
    int x0 = (int)fx0, y0 = (int)fy0;

    __shared__ float tgt[128];
    __shared__ float G[64];
    int tid = threadIdx.x;
    tgt[tid]      = ffeats[(((size_t)(pl * 8 + s)) * 128 + n) * 128 + tid];
    tgt[tid + 64] = ffeats[(((size_t)(pl * 8 + s)) * 128 + n) * 128 + tid + 64];
    __syncthreads();

    int ix = tid & 7, iy = tid >> 3;
    int px = x0 - 3 + ix, py = y0 - 3 + iy;
    float dot = 0.0f;
    if (px >= 0 && px < size && py >= 0 && py < size) {
        size_t cs = (size_t)size * size;
        const float* fp = fm + ((size_t)s * 128) * cs + (size_t)py * size + px;
        #pragma unroll 8
        for (int c = 0; c < 128; c++) dot += tgt[c] * fp[(size_t)c * cs];
    }
    G[iy * 8 + ix] = dot * 0.08838834764831845f;
    __syncthreads();

    if (tid < 49) {
        int kx = tid / 7, ky = tid % 7;
        float g00 = G[ky * 8 + kx];
        float g10 = G[ky * 8 + kx + 1];
        float g01 = G[(ky + 1) * 8 + kx];
        float g11 = G[(ky + 1) * 8 + kx + 1];
        float v = g00 * (1 - wx) * (1 - wy) + g10 * wx * (1 - wy) +
                  g01 * (1 - wx) * wy + g11 * wx * wy;
        tin[(size_t)(n * 8 + s) * 1169 + 195 + pl * 196 + lvl * 49 + tid] = v;
    }
}

__global__ void k_assemble(float* __restrict__ tin, const float* __restrict__ coords,
                           const float* __restrict__ ffeats, const float* __restrict__ pos,
                           const float* __restrict__ tim, const float* __restrict__ track_mask,
                           const float* __restrict__ vis_init) {
    int ns = blockIdx.x;
    int n = ns >> 3, s = ns & 7;
    __shared__ float f[3];
    if (threadIdx.x < 3)
        f[threadIdx.x] = coords[(s * 128 + n) * 3 + threadIdx.x] - coords[n * 3 + threadIdx.x];
    __syncthreads();
    size_t row = (size_t)(n * 8 + s) * 1169;
    for (int col = threadIdx.x; col < 1169; col += blockDim.x) {
        float v;
        if (col < 192) {
            int a = col / 64, r = col % 64, q = r >> 1;
            float ang = f[a] * (31.25f * (float)q);
            v = (r & 1) ? cosf(ang) : sinf(ang);
        } else if (col < 195) {
            v = f[col - 192];
        } else if (col < 783) {
            v = tin[row + col];
        } else if (col < 1167) {
            int c = col - 783;
            int k = c >> 7, cc = c & 127;
            v = ffeats[(((size_t)(k * 8 + s)) * 128 + n) * 128 + cc];
        } else {
            int c2 = col - 1167;
            int fidx = n * 16 + s * 2 + c2;
            int p = fidx >> 3, sp = fidx & 7;
            v = (p < 128) ? track_mask[sp * 128 + p] : vis_init[sp * 128 + (p - 128)];
        }
        tin[row + col] = v + pos[(size_t)n * 1169 + col] + tim[(size_t)s * 1169 + col];
    }
}

// ------------------------- tensor-core GEMM --------------------------------
// C[M,N] = act(A[M,K] @ B[K,N] + bias) + resid, fp32 in/out.
// bf16 hi/lo split (3 products) on wmma 16x16x16 with fp32 accumulate.
// Register-prefetch pipeline: next k-tile's LDGs issued before the MMA block.
// BM in {128, 64}; BN=64; BK=32. 8 warps/block. Batched via blockIdx.z.
template<int BM>
__global__ __launch_bounds__(256) void gemm_wmma_k(
    const float* __restrict__ A, const float* __restrict__ B,
    const float* __restrict__ bias, const float* __restrict__ resid,
    float* __restrict__ C, int M, int N, int K, int act,
    size_t As_, size_t Bs_, size_t bs_, size_t Cs_) {
    constexpr int BN = 64, BK = 32;
    constexpr int MW = BM / 32;          // warps along M
    constexpr int NW = 8 / MW;           // warps along N
    constexpr int FN = BN / (16 * NW);   // 16-col frags per warp
    constexpr int LDA = BK + 8;          // 40 bf16 (80B)
    constexpr int LDB = BN + 8;          // 72 bf16 (144B)
    constexpr int LDC = BN + 4;          // 68 f32 (272B)
    constexpr int RA = BM * BK / 256;    // A elems per thread (16 / 8)
    constexpr int RB = BK * BN / 256;    // B elems per thread (8)
    constexpr size_t STAGE = (size_t)BM * LDA * 2 * 2 + (size_t)BK * LDB * 2 * 2;
    constexpr size_t CBUF  = (size_t)BM * LDC * 4;
    constexpr size_t SBYTES = STAGE > CBUF ? STAGE : CBUF;
    __shared__ __align__(256) unsigned char smem_raw[SBYTES];
    __nv_bfloat16* sAh = (__nv_bfloat16*)smem_raw;
    __nv_bfloat16* sAl = sAh + BM * LDA;
    __nv_bfloat16* sBh = sAl + BM * LDA;
    __nv_bfloat16* sBl = sBh + BK * LDB;
    float* Cbuf = (float*)smem_raw;      // aliases stage; used after k-loop

    int z = blockIdx.z;
    A += (size_t)z * As_;
    B += (size_t)z * Bs_;
    if (bias) bias += (size_t)z * bs_;
    C += (size_t)z * Cs_;

    int tid = threadIdx.x;
    int w = tid >> 5;
    int wm = w / NW, wn = w % NW;
    int m0 = blockIdx.y * BM, n0 = blockIdx.x * BN;

    wmma::fragment<wmma::accumulator, 16, 16, 16, float> acc[2][FN];
    #pragma unroll
    for (int i = 0; i < 2; i++)
        #pragma unroll
        for (int j = 0; j < FN; j++) wmma::fill_fragment(acc[i][j], 0.0f);

    float ra[RA], rb[RB];
    // prologue: k-tile 0 -> registers
    #pragma unroll
    for (int r = 0; r < RA; r++) {
        int idx = tid + r * 256;
        int i = idx >> 5, j = idx & 31;
        int mm = m0 + i;
        ra[r] = (mm < M && j < K) ? A[(size_t)mm * K + j] : 0.0f;
    }
    #pragma unroll
    for (int r = 0; r < RB; r++) {
        int idx = tid + r * 256;
        int i = idx >> 6, j = idx & 63;
        int nn = n0 + j;
        rb[r] = (i < K && nn < N) ? B[(size_t)i * N + nn] : 0.0f;
    }

    for (int k0 = 0; k0 < K; k0 += BK) {
        // commit registers -> smem with hi/lo split
        #pragma unroll
        for (int r = 0; r < RA; r++) {
            int idx = tid + r * 256;
            int i = idx >> 5, j = idx & 31;
            float a = ra[r];
            __nv_bfloat16 h = __float2bfloat16(a);
            sAh[i * LDA + j] = h;
            sAl[i * LDA + j] = __float2bfloat16(a - __bfloat162float(h));
        }
        #pragma unroll
        for (int r = 0; r < RB; r++) {
            int idx = tid + r * 256;
            int i = idx >> 6, j = idx & 63;
            float b = rb[r];
            __nv_bfloat16 h = __float2bfloat16(b);
            sBh[i * LDB + j] = h;
            sBl[i * LDB + j] = __float2bfloat16(b - __bfloat162float(h));
        }
        __syncthreads();
        // prefetch next k-tile (overlaps the MMA block below)
        int kn = k0 + BK;
        if (kn < K) {
            #pragma unroll
            for (int r = 0; r < RA; r++) {
                int idx = tid + r * 256;
                int i = idx >> 5, j = idx & 31;
                int mm = m0 + i, kk = kn + j;
                ra[r] = (mm < M && kk < K) ? A[(size_t)mm * K + kk] : 0.0f;
            }
            #pragma unroll
            for (int r = 0; r < RB; r++) {
                int idx = tid + r * 256;
                int i = idx >> 6, j = idx & 63;
                int kb = kn + i, nn = n0 + j;
                rb[r] = (kb < K && nn < N) ? B[(size_t)kb * N + nn] : 0.0f;
            }
        }
        #pragma unroll
        for (int ks = 0; ks < 2; ks++) {
            int kk = ks * 16;
            wmma::fragment<wmma::matrix_a, 16, 16, 16, __nv_bfloat16, wmma::row_major> ah[2], al[2];
            wmma::fragment<wmma::matrix_b, 16, 16, 16, __nv_bfloat16, wmma::row_major> bh[FN], bl[FN];
            #pragma unroll
            for (int i = 0; i < 2; i++) {
                int r = wm * 32 + i * 16;
                wmma::load_matrix_sync(ah[i], sAh + r * LDA + kk, LDA);
                wmma::load_matrix_sync(al[i], sAl + r * LDA + kk, LDA);
            }
            #pragma unroll
            for (int j = 0; j < FN; j++) {
                int c = (wn * FN + j) * 16;
                wmma::load_matrix_sync(bh[j], sBh + kk * LDB + c, LDB);
                wmma::load_matrix_sync(bl[j], sBl + kk * LDB + c, LDB);
            }
            #pragma unroll
            for (int i = 0; i < 2; i++)
                #pragma unroll
                for (int j = 0; j < FN; j++) {
                    wmma::mma_sync(acc[i][j], ah[i], bh[j], acc[i][j]);
                    wmma::mma_sync(acc[i][j], ah[i], bl[j], acc[i][j]);
                    wmma::mma_sync(acc[i][j], al[i], bh[j], acc[i][j]);
                }
        }
        __syncthreads();
    }
    // stage accumulators to smem (stage no longer needed; k-loop ended with a barrier)
    #pragma unroll
    for (int i = 0; i < 2; i++)
        #pragma unroll
        for (int j = 0; j < FN; j++)
            wmma::store_matrix_sync(Cbuf + (wm * 32 + i * 16) * LDC + (wn * FN + j) * 16,
                                    acc[i][j], LDC, wmma::mem_row_major);
    __syncthreads();
    for (int idx = tid; idx < BM * BN; idx += 256) {
        int i = idx >> 6, j = idx & 63;
        int row = m0 + i, col = n0 + j;
        if (row >= M || col >= N) continue;
        float v = Cbuf[i * LDC + j];
        if (bias)  v += bias[col];
        if (act == 1) v = 0.5f * v * (1.0f + erff(v * 0.70710678118654752f));
        if (resid) v += resid[(size_t)row * N + col];
        C[(size_t)row * N + col] = v;
    }
}

static inline void gemm(const float* A, const float* B, const float* bias,
                        const float* resid, float* C,
                        int M, int N, int K, int act) {
    int nb = (N + 63) / 64;
    int mb128 = (M + 127) / 128;
    if (nb * mb128 >= 120) {
        dim3 g(nb, mb128, 1);
        gemm_wmma_k<128><<<g, 256>>>(A, B, bias, resid, C, M, N, K, act, 0, 0, 0, 0);
    } else {
        dim3 g(nb, (M + 63) / 64, 1);
        gemm_wmma_k<64><<<g, 256>>>(A, B, bias, resid, C, M, N, K, act, 0, 0, 0, 0);
    }
}

static inline void gemm_batched3(const float* A, const float* B, const float* bias,
                                 float* C, int M, int N, int K, int act,
                                 size_t As_, size_t Bs_, size_t bs_, size_t Cs_) {
    dim3 g((N + 63) / 64, (M + 63) / 64, 3);
    gemm_wmma_k<64><<<g, 256>>>(A, B, bias, nullptr, C, M, N, K, act, As_, Bs_, bs_, Cs_);
}

// ---------------------------------------------------------------------------

// Fused: support += sproj*0.01  AND  biasin = b_in + mean(sproj)*... (pre-update sproj)
// Grid 152 x 256: idx < 38400 -> support update; idx in [38400, 38784) -> bias column.
__global__ void k_spfix(float* __restrict__ support, const float* __restrict__ sproj,
                        const float* __restrict__ b_in, float* __restrict__ biasin) {
    int idx = blockIdx.x * blockDim.x + threadIdx.x;
    if (idx < 38400) {
        support[idx] += sproj[idx] * 0.01f;
    } else if (idx < 38784) {
        int c = idx - 38400;
        float s = 0.0f;
        for (int r = 0; r < 100; r++) s += sproj[r * 384 + c];
        biasin[c] = b_in[c] + s * 0.01f;
    }
}

// LayerNorm over 384 cols, one warp per row. Grid = 1024/4 = 256, block = 128.
__global__ __launch_bounds__(128) void k_norm384(const float* __restrict__ x,
                                                 float* __restrict__ y,
                                                 const float* __restrict__ gw,
                                                 const float* __restrict__ bw) {
    int r = blockIdx.x * 4 + (threadIdx.x >> 5);
    int lane = threadIdx.x & 31;
    const float* xp = x + (size_t)r * 384;
    float v[12];
    float s = 0.0f, ss = 0.0f;
    #pragma unroll
    for (int i = 0; i < 12; i++) {
        v[i] = xp[lane + i * 32];
        s += v[i];
        ss += v[i] * v[i];
    }
    #pragma unroll
    for (int o = 16; o; o >>= 1) {
        s += __shfl_xor_sync(0xffffffffu, s, o);
        ss += __shfl_xor_sync(0xffffffffu, ss, o);
    }
    float m = s * (1.0f / 384.0f);
    float var = ss * (1.0f / 384.0f) - m * m;
    float inv = rsqrtf(var + 1e-5f);
    float* yp = y + (size_t)r * 384;
    #pragma unroll
    for (int i = 0; i < 12; i++)
        yp[lane + i * 32] = (v[i] - m) * inv * gw[lane + i * 32] + bw[lane + i * 32];
}

// Batched GroupNorm for the 3 feature-update chains + fused coords update.
// One warp per (k, row); blocks 0..23 additionally apply the coords delta.
__global__ __launch_bounds__(128) void k_norm3(const float* __restrict__ del,
                                               const float* __restrict__ gn_g,
                                               const float* __restrict__ gn_b,
                                               float* __restrict__ gn,
                                               float* __restrict__ coords) {
    // fused coords += delta[..., :3] (3072 elements over blocks 0..23)
    int cidx = blockIdx.x * 128 + threadIdx.x;
    if (cidx < 3072) {
        int sn = cidx / 3, a = cidx % 3;
        int s = sn >> 7, n = sn & 127;
        coords[cidx] += del[(size_t)(n * 8 + s) * 387 + a];
    }
    int row4 = blockIdx.x * 4 + (threadIdx.x >> 5);
    int k = row4 / 1024, r = row4 % 1024;
    int lane = threadIdx.x & 31;
    const float* xp = del + (size_t)r * 387 + 3 + k * 128;
    float v0 = xp[lane], v1 = xp[lane + 32], v2 = xp[lane + 64], v3 = xp[lane + 96];
    float s = v0 + v1 + v2 + v3;
    float ss = v0 * v0 + v1 * v1 + v2 * v2 + v3 * v3;
    #pragma unroll
    for (int o = 16; o; o >>= 1) {
        s += __shfl_xor_sync(0xffffffffu, s, o);
        ss += __shfl_xor_sync(0xffffffffu, ss, o);
    }
    float m = s / 128.0f;
    float var = ss / 128.0f - m * m;
    float inv = rsqrtf(var + 1e-5f);
    const float* g = gn_g + k * 128;
    const float* b = gn_b + k * 128;
    float* yp = gn + (size_t)k * 131072 + (size_t)r * 128;
    yp[lane]      = (v0 - m) * inv * g[lane]      + b[lane];
    yp[lane + 32] = (v1 - m) * inv * g[lane + 32] + b[lane + 32];
    yp[lane + 64] = (v2 - m) * inv * g[lane + 64] + b[lane + 64];
    yp[lane + 96] = (v3 - m) * inv * g[lane + 96] + b[lane + 96];
}

__global__ __launch_bounds__(64) void k_attn8(const float* __restrict__ qkv,
                                              float* __restrict__ o) {
    int m = blockIdx.x;
    __shared__ float sm[8 * 1152];
    int tid = threadIdx.x;
    for (int i = tid; i < 8 * 1152; i += 64)
        sm[i] = qkv[(size_t)(m * 8 + i / 1152) * 1152 + (i % 1152)];
    __syncthreads();
    int h = tid >> 3, t = tid & 7;
    const float* q = sm + t * 1152 + h * 48;
    float sc[8];
    float mx = -1e30f;
    #pragma unroll
    for (int u = 0; u < 8; u++) {
        const float* kk = sm + u * 1152 + 384 + h * 48;
        float d = 0.0f;
        #pragma unroll
        for (int j = 0; j < 48; j++) d += q[j] * kk[j];
        d *= 0.14433756729740643f;
        sc[u] = d;
        mx = fmaxf(mx, d);
    }
    float sum = 0.0f;
    #pragma unroll
    for (int u = 0; u < 8; u++) { sc[u] = expf(sc[u] - mx); sum += sc[u]; }
    float inv = 1.0f / sum;
    for (int j = 0; j < 48; j++) {
        float a = 0.0f;
        #pragma unroll
        for (int u = 0; u < 8; u++) a += sc[u] * sm[u * 1152 + 768 + h * 48 + j];
        o[(size_t)(m * 8 + t) * 384 + h * 48 + j] = a * inv;
    }
}

__global__ __launch_bounds__(128) void k_attn128(const float* __restrict__ qkv,
                                                 float* __restrict__ o) {
    int s = blockIdx.x >> 3, h = blockIdx.x & 7;
    __shared__ float ks[128 * 48];
    __shared__ float vs[64 * 48];
    int t = threadIdx.x;
    for (int i = t; i < 128 * 48; i += 128) {
        int u = i / 48, j = i % 48;
        ks[i] = qkv[(size_t)(u * 8 + s) * 1152 + 384 + h * 48 + j];
    }
    __syncthreads();
    float q[48];
    size_t qrow = (size_t)(t * 8 + s) * 1152 + h * 48;
    #pragma unroll
    for (int j = 0; j < 48; j++) q[j] = qkv[qrow + j];
    const float scale = 0.14433756729740643f;
    float mx = -1e30f;
    for (int u = 0; u < 128; u++) {
        float d = 0.0f;
        #pragma unroll
        for (int j = 0; j < 48; j++) d += q[j] * ks[u * 48 + j];
        mx = fmaxf(mx, d * scale);
    }
    float sum = 0.0f;
    float out[48];
    #pragma unroll
    for (int j = 0; j < 48; j++) out[j] = 0.0f;
    for (int ch = 0; ch < 2; ch++) {
        __syncthreads();
        for (int i = t; i < 64 * 48; i += 128) {
            int u = i / 48, j = i % 48;
            vs[i] = qkv[(size_t)((ch * 64 + u) * 8 + s) * 1152 + 768 + h * 48 + j];
        }
        __syncthreads();
        for (int u = 0; u < 64; u++) {
            float d = 0.0f;
            const float* kp = ks + (ch * 64 + u) * 48;
            #pragma unroll
            for (int j = 0; j < 48; j++) d += q[j] * kp[j];
            float p = expf(d * scale - mx);
            sum += p;
            #pragma unroll
            for (int j = 0; j < 48; j++) out[j] += p * vs[u * 48 + j];
        }
    }
    float inv = 1.0f / sum;
    size_t orow = (size_t)(t * 8 + s) * 384 + h * 48;
    #pragma unroll
    for (int j = 0; j < 48; j++) o[orow + j] = out[j] * inv;
}

__global__ void k_ffadd3(float* __restrict__ ffeats, const float* __restrict__ upd) {
    int idx = blockIdx.x * blockDim.x + threadIdx.x;
    if (idx >= 393216) return;
    int k = idx / 131072;
    int r = idx % 131072;
    int n = r >> 10;
    int s = (r >> 7) & 7;
    int c = r & 127;
    ffeats[(((size_t)(k * 8 + s)) * 128 + n) * 128 + c] += upd[idx];
}

__global__ void k_vis(const float* __restrict__ ffeats, const float* __restrict__ coords,
                      const float* __restrict__ Wvis, const float* __restrict__ bvis,
                      float* __restrict__ out) {
    int sn = blockIdx.x;
    int s = sn >> 7, n = sn & 127;
    float acc = 0.0f;
    for (int c = threadIdx.x; c < 384; c += blockDim.x) {
        int k = c >> 7, cc = c & 127;
        acc += ffeats[(((size_t)(k * 8 + s)) * 128 + n) * 128 + cc] * Wvis[c];
    }
    __shared__ float sh[32];
    int lane = threadIdx.x & 31, w = threadIdx.x >> 5;
    #pragma unroll
    for (int o = 16; o; o >>= 1) acc += __shfl_down_sync(0xffffffffu, acc, o);
    if (lane == 0) sh[w] = acc;
    __syncthreads();
    if (threadIdx.x == 0) {
        float t = 0.0f;
        int nw = blockDim.x >> 5;
        for (int i = 0; i < nw; i++) t += sh[i];
        out[sn * 4 + 3] = t + bvis[0];
    }
    if (threadIdx.x < 3) out[sn * 4 + threadIdx.x] = coords[sn * 3 + threadIdx.x];
}

// ------------------------------- host --------------------------------------

extern "C" void kernel_launch(void* const* d_in, const int* in_sizes, int n_in,
                              void* d_out, int out_size) {
    const float* fmXY        = (const float*)d_in[0];
    const float* fmYZ        = (const float*)d_in[1];
    const float* fmXZ        = (const float*)d_in[2];
    const float* coords_init = (const float*)d_in[3];
    const float* vis_init    = (const float*)d_in[4];
    const float* track_mask  = (const float*)d_in[5];
    const float* feat_init   = (const float*)d_in[6];
    const float* support_in  = (const float*)d_in[7];
    int i8 = (in_sizes[8] == 1) ? 9 : 8;
    const float* W_in  = (const float*)d_in[i8 + 0];
    const float* b_in  = (const float*)d_in[i8 + 1];
    const float* lnp   = (const float*)d_in[i8 + 2];
    const float* Wqkv  = (const float*)d_in[i8 + 3];
    const float* bqkv  = (const float*)d_in[i8 + 4];
    const float* Wo    = (const float*)d_in[i8 + 5];
    const float* bo    = (const float*)d_in[i8 + 6];
    const float* W1    = (const float*)d_in[i8 + 7];
    const float* b1    = (const float*)d_in[i8 + 8];
    const float* W2    = (const float*)d_in[i8 + 9];
    const float* b2    = (const float*)d_in[i8 + 10];
    const float* W_out = (const float*)d_in[i8 + 11];
    const float* b_out = (const float*)d_in[i8 + 12];
    const float* Ws    = (const float*)d_in[i8 + 13];
    const float* bs    = (const float*)d_in[i8 + 14];
    const float* gn_g  = (const float*)d_in[i8 + 15];
    const float* gn_b  = (const float*)d_in[i8 + 16];
    const float* Wu    = (const float*)d_in[i8 + 17];
    const float* bu    = (const float*)d_in[i8 + 18];
    const float* Wvis  = (const float*)d_in[i8 + 19];
    const float* bvis  = (const float*)d_in[i8 + 20];
    float* out = (float*)d_out;

    float* sc = nullptr;
    cudaGetSymbolAddress((void**)&sc, g_scratch);
    float* PYR = sc + OFF_PYR;
    float* FF  = sc + OFF_FFEATS;
    float* CR  = sc + OFF_COORDS;
    float* SUP = sc + OFF_SUPPORT;
    float* SPJ = sc + OFF_SPROJ;
    float* BIN = sc + OFF_BIASIN;
    float* POS = sc + OFF_POS;
    float* TIM = sc + OFF_TIMES;
    float* TIN = sc + OFF_TIN;
    float* H   = sc + OFF_H;
    float* YLN = sc + OFF_YLN;
    float* QKV = sc + OFF_QKV;
    float* AO  = sc + OFF_ATTNO;
    float* MLP = sc + OFF_MLP;
    float* DEL = sc + OFF_DELTA;
    float* GN  = sc + OFF_GN;
    float* UPD = sc + OFF_UPD;

    const float* fms[3] = {fmXY, fmYZ, fmXZ};
    for (int pl = 0; pl < 3; pl++) {
        float* p1 = PYR + (size_t)pl * PYR_PLANE;
        float* p2 = p1 + 4194304;
        float* p3 = p2 + 1048576;
        k_down<<<(1024 * 64 * 64 + 255) / 256, 256>>>(fms[pl], p1, 64, 64);
        k_down<<<(1024 * 32 * 32 + 255) / 256, 256>>>(p1, p2, 32, 32);
        k_down<<<(1024 * 16 * 16 + 255) / 256, 256>>>(p2, p3, 16, 16);
    }
    k_pos<<<128, 256>>>(coords_init, POS);
    k_times<<<8, 256>>>(TIM);
    k_init<<<768, 512>>>(coords_init, support_in, feat_init, CR, SUP, FF);

    for (int it = 0; it < 2; it++) {
        k_corr<<<12288, 64>>>(fmXY, fmYZ, fmXZ, PYR, FF, CR, TIN);
        k_assemble<<<1024, 128>>>(TIN, CR, FF, POS, TIM, track_mask, vis_init);

        gemm(SUP, Ws, bs, nullptr, SPJ, 100, 384, 384, 0);
        k_spfix<<<152, 256>>>(SUP, SPJ, b_in, BIN);

        gemm(TIN, W_in, BIN, nullptr, H, 1024, 384, 1169, 0);

        for (int i = 0; i < 6; i++) {
            const float* Wq  = Wqkv + (size_t)i * 384 * 1152;
            const float* bq  = bqkv + (size_t)i * 1152;
            const float* Woi = Wo   + (size_t)i * 384 * 384;
            const float* boi = bo   + (size_t)i * 384;
            const float* W1i = W1   + (size_t)i * 384 * 1536;
            const float* b1i = b1   + (size_t)i * 1536;
            const float* W2i = W2   + (size_t)i * 1536 * 384;
            const float* b2i = b2   + (size_t)i * 384;
            const float* ln  = lnp  + (size_t)i * 4 * 384;

            k_norm384<<<256, 128>>>(H, YLN, ln, ln + 384);
            gemm(YLN, Wq, bq, nullptr, QKV, 1024, 1152, 384, 0);
            if ((i & 1) == 0) k_attn8<<<128, 64>>>(QKV, AO);
            else              k_attn128<<<64, 128>>>(QKV, AO);
            gemm(AO, Woi, boi, H, H, 1024, 384, 384, 0);

            k_norm384<<<256, 128>>>(H, YLN, ln + 768, ln + 1152);
            gemm(YLN, W1i, b1i, nullptr, MLP, 1024, 1536, 384, 1);
            gemm(MLP, W2i, b2i, H, H, 1024, 384, 1536, 0);
        }

        gemm(H, W_out, b_out, nullptr, DEL, 1024, 387, 384, 0);
        k_norm3<<<768, 128>>>(DEL, gn_g, gn_b, GN, CR);
        gemm_batched3(GN, Wu, bu, UPD, 1024, 128, 128, 1,
                      131072, 16384, 128, 131072);
        k_ffadd3<<<1536, 256>>>(FF, UPD);
    }
    k_vis<<<1024, 128>>>(FF, CR, Wvis, bvis, out);
}